// round 4
// baseline (speedup 1.0000x reference)
#include <cuda_runtime.h>
#include <math.h>

#define BB 32
#define NN 128
#define FF 10
#define DD 64
#define TK 20
#define EX 25
#define BNN 4096           // B*N
#define G2 8192            // 2*BN
#define NE (BNN*EX)        // 102400 candidate edges in layer 2
#define NSLICE 8

// ---------------- scratch (device globals: allocation-free) ----------------
__device__ float d_h[BNN*DD];
__device__ float d_si[BNN], d_sj[BNN];
__device__ float d_ei[NN], d_ej[NN], d_invn1[NN];
__device__ int   d_topi1[NN*TK];
__device__ float d_topv1[NN*TK];
__device__ float d_agg[BNN*DD];
__device__ float d_scale1[DD], d_shift1[DD];
__device__ float d_g[BNN*DD];               // gcn rows only
__device__ float d_efp[NSLICE*BNN*DD];      // ef partial sums per K-slice
__device__ float d_gn[G2*DD];               // row-normalized [gcn; ef]
__device__ float d_h2[BNN*DD];
__device__ float d_hi2[BNN], d_hj2[BNN];
__device__ float d_S[(size_t)BNN*G2];       // 128 MB cosine-score matrix
__device__ int   d_topi2[NE];
__device__ float d_topv2[NE];
__device__ int   d_cnt[BNN];
__device__ int   d_cur[BNN];
__device__ int   d_off[BNN+1];
__device__ int   d_eid[NE];
__device__ float d_sc2[NE];
__device__ float d_agg2[BNN*DD];
__device__ float d_x3[BNN*DD];
__device__ float d_scale2[DD], d_shift2[DD];

// ---------------- helpers ----------------
__device__ __forceinline__ float lrelu(float x){ return x >= 0.f ? x : 0.2f*x; }

typedef unsigned long long ull;
__device__ __forceinline__ ull ffma2(ull a, ull b, ull c){
    ull d; asm("fma.rn.f32x2 %0, %1, %2, %3;" : "=l"(d) : "l"(a), "l"(b), "l"(c));
    return d;
}
__device__ __forceinline__ ull rep2(float x){
    ull d; asm("mov.b64 %0, {%1, %1};" : "=l"(d) : "r"(__float_as_uint(x)));
    return d;
}

// ---------------- K0: zero CSR counters ----------------
__global__ void k_zero(){
    int idx = blockIdx.x*256 + threadIdx.x;      // 17*256 = 4352
    if(idx < BNN){ d_cnt[idx] = 0; d_cur[idx] = 0; }
}

// ---------------- K1: emb norms + embedding parts of attention keys ----------
__global__ void k_embprep(const float* __restrict__ emb,
                          const float* __restrict__ ai1,
                          const float* __restrict__ aj1){
    int n = blockIdx.x, t = threadIdx.x;
    float e  = emb[n*DD + t];
    float ss = e*e, vi = e*ai1[DD+t], vj = e*aj1[DD+t];
    __shared__ float sb[6];
    #pragma unroll
    for(int o=16;o>0;o>>=1){
        ss += __shfl_down_sync(0xffffffffu, ss, o);
        vi += __shfl_down_sync(0xffffffffu, vi, o);
        vj += __shfl_down_sync(0xffffffffu, vj, o);
    }
    if((t&31)==0){ int w=t>>5; sb[w]=ss; sb[2+w]=vi; sb[4+w]=vj; }
    __syncthreads();
    if(t==0){
        float nrm = sqrtf(sb[0]+sb[1]);
        d_invn1[n] = 1.f/fmaxf(nrm, 1e-12f);
        d_ei[n] = sb[2]+sb[3];
        d_ej[n] = sb[4]+sb[5];
    }
}

// ---------------- K2: cosine(emb,emb) + top-20 per node ----------------
__global__ void k_cos1(const float* __restrict__ emb){
    int i = blockIdx.x, t = threadIdx.x;            // 128 threads
    __shared__ float se[DD];
    __shared__ float sc[NN];
    __shared__ float rv[NN];
    __shared__ int   ridx[NN];
    if(t < DD) se[t] = emb[i*DD + t];
    __syncthreads();
    float dp = 0.f;
    #pragma unroll
    for(int d=0; d<DD; d++) dp += se[d]*emb[t*DD + d];
    sc[t] = dp * d_invn1[i] * d_invn1[t];
    __syncthreads();
    for(int it=0; it<TK; it++){
        rv[t] = sc[t]; ridx[t] = t;
        __syncthreads();
        for(int s=64; s>0; s>>=1){
            if(t < s){
                float v2 = rv[t+s]; int i2 = ridx[t+s];
                if(v2 > rv[t] || (v2 == rv[t] && i2 < ridx[t])){ rv[t]=v2; ridx[t]=i2; }
            }
            __syncthreads();
        }
        if(t==0){
            d_topv1[i*TK+it] = rv[0];
            d_topi1[i*TK+it] = ridx[0];
            sc[ridx[0]] = -INFINITY;
        }
        __syncthreads();
    }
}

// ---------------- K3: h = x@W1, si/sj scalars (4 rows/block) ----------------
__global__ void k_h(const float* __restrict__ data, const float* __restrict__ W1,
                    const float* __restrict__ ai1, const float* __restrict__ aj1){
    int t = threadIdx.x;
    int g = t>>6, d = t&63;
    int r = blockIdx.x*4 + g;
    __shared__ float sx[4][FF];
    __shared__ float svi[8], svj[8];
    if(d < FF) sx[g][d] = data[r*FF + d];
    __syncthreads();
    float h = 0.f;
    #pragma unroll
    for(int f=0; f<FF; f++) h += sx[g][f]*W1[f*DD + d];
    d_h[r*DD + d] = h;
    float vi = h*ai1[d], vj = h*aj1[d];
    #pragma unroll
    for(int o=16;o>0;o>>=1){
        vi += __shfl_down_sync(0xffffffffu, vi, o);
        vj += __shfl_down_sync(0xffffffffu, vj, o);
    }
    if((t&31)==0){ svi[t>>5]=vi; svj[t>>5]=vj; }
    __syncthreads();
    if(d==0){
        d_si[r] = svi[2*g]+svi[2*g+1] + d_ei[r & (NN-1)];
        d_sj[r] = svj[2*g]+svj[2*g+1] + d_ej[r & (NN-1)];
    }
}

// ---------------- K4: layer-1 edge softmax + aggregation (4 rows/block) -----
__global__ void k_attn1(const float* __restrict__ bias1){
    int t = threadIdx.x;
    int g = t>>6, d = t&63;
    int r = blockIdx.x*4 + g;
    int b = r >> 7, i = r & (NN-1);
    __shared__ int   ssrc[4][TK];
    __shared__ float sal[4][TK];
    if(d < TK){
        int sn = d_topi1[i*TK + d];
        int s  = (b<<7) + sn;
        ssrc[g][d] = s;
        sal[g][d]  = lrelu(d_si[r] + d_sj[s]) * d_topv1[i*TK + d];
    }
    __syncthreads();
    if(d == 0){
        float m = -INFINITY;
        for(int k=0;k<TK;k++) m = fmaxf(m, sal[g][k]);
        float e[TK], sum = 0.f;
        for(int k=0;k<TK;k++){ e[k] = expf(sal[g][k]-m); sum += e[k]; }
        float inv = 1.f/fmaxf(sum, 1e-12f);
        for(int k=0;k<TK;k++) sal[g][k] = e[k]*inv;
    }
    __syncthreads();
    float a = 0.f;
    #pragma unroll
    for(int k=0;k<TK;k++) a += sal[g][k]*d_h[ssrc[g][k]*DD + d];
    d_agg[r*DD + d] = a + bias1[d];
}

// ---------------- batchnorm stats (two-pass, per channel) ----------------
__global__ void k_stats1(const float* __restrict__ gamma, const float* __restrict__ beta){
    int d = blockIdx.x, t = threadIdx.x;            // 256 threads
    __shared__ float sb[8];
    __shared__ float smu;
    float s = 0.f;
    for(int r=t; r<BNN; r+=256) s += d_agg[r*DD + d];
    #pragma unroll
    for(int o=16;o>0;o>>=1) s += __shfl_down_sync(0xffffffffu, s, o);
    if((t&31)==0) sb[t>>5] = s;
    __syncthreads();
    if(t==0){ float tot=0; for(int w=0;w<8;w++) tot+=sb[w]; smu = tot*(1.f/BNN); }
    __syncthreads();
    float mu = smu;
    float q = 0.f;
    for(int r=t; r<BNN; r+=256){ float x = d_agg[r*DD + d] - mu; q += x*x; }
    #pragma unroll
    for(int o=16;o>0;o>>=1) q += __shfl_down_sync(0xffffffffu, q, o);
    if((t&31)==0) sb[t>>5] = q;
    __syncthreads();
    if(t==0){
        float tot=0; for(int w=0;w<8;w++) tot+=sb[w];
        float var = tot*(1.f/BNN);
        float sc  = gamma[d]/sqrtf(var + 1e-5f);
        d_scale1[d] = sc; d_shift1[d] = beta[d] - mu*sc;
    }
}

__global__ void k_bnrelu(){
    int idx = blockIdx.x*256 + threadIdx.x;
    int d = idx & 63;
    d_g[idx] = fmaxf(d_scale1[d]*d_agg[idx] + d_shift1[d], 0.f);
}

// ---------------- K8: ef = P^T @ gcn, FFMA2, per-slice partials -------------
__global__ void k_ef(const float* __restrict__ P){
    __shared__ float As[64][68];   // [k_local][j_local] = P[k][j]
    __shared__ float Bs[64][68];   // [k_local][d]       = gcn[k][d]
    int t = threadIdx.x;
    int j0 = blockIdx.x*64;
    int slice = blockIdx.y;
    int tx = t & 7, ty = t >> 3;   // tx: d octet, ty: j pair
    ull cp[2][4] = {};
    for(int cc=0; cc<8; cc++){
        int ib = slice*512 + cc*64;
        #pragma unroll
        for(int u=0; u<4; u++){
            int f = t*4 + u; int rr = f>>4; int cq = f&15;
            *(float4*)&As[rr][cq*4] = *(const float4*)&P[(size_t)(ib+rr)*BNN + j0 + cq*4];
            *(float4*)&Bs[rr][cq*4] = *(const float4*)&d_g[(ib+rr)*DD + cq*4];
        }
        __syncthreads();
        #pragma unroll
        for(int k=0; k<64; k++){
            float2 a = *(float2*)&As[k][ty*2];
            ull a0 = rep2(a.x), a1 = rep2(a.y);
            ulonglong2 b01 = *(ulonglong2*)&Bs[k][tx*8];
            ulonglong2 b23 = *(ulonglong2*)&Bs[k][tx*8+4];
            cp[0][0]=ffma2(a0,b01.x,cp[0][0]); cp[0][1]=ffma2(a0,b01.y,cp[0][1]);
            cp[0][2]=ffma2(a0,b23.x,cp[0][2]); cp[0][3]=ffma2(a0,b23.y,cp[0][3]);
            cp[1][0]=ffma2(a1,b01.x,cp[1][0]); cp[1][1]=ffma2(a1,b01.y,cp[1][1]);
            cp[1][2]=ffma2(a1,b23.x,cp[1][2]); cp[1][3]=ffma2(a1,b23.y,cp[1][3]);
        }
        __syncthreads();
    }
    float* outp = &d_efp[(size_t)slice*BNN*DD];
    #pragma unroll
    for(int m=0;m<2;m++){
        int row = j0 + ty*2 + m;
        ulonglong2 o1; o1.x = cp[m][0]; o1.y = cp[m][1];
        ulonglong2 o2; o2.x = cp[m][2]; o2.y = cp[m][3];
        *(ulonglong2*)&outp[row*DD + tx*8]     = o1;
        *(ulonglong2*)&outp[row*DD + tx*8 + 4] = o2;
    }
}

// ---------------- K9: row-normalize [gcn; ef] (4 rows/block) ----------------
__global__ void k_gnorm(){
    int t = threadIdx.x;
    int g = t>>6, d = t&63;
    int r = blockIdx.x*4 + g;
    __shared__ float sb[8];
    float v;
    if(r < BNN) v = d_g[r*DD + d];
    else {
        int rr = r - BNN;
        v = 0.f;
        #pragma unroll
        for(int s=0; s<NSLICE; s++) v += d_efp[(size_t)s*BNN*DD + rr*DD + d];
    }
    float ss = v*v;
    #pragma unroll
    for(int o=16;o>0;o>>=1) ss += __shfl_down_sync(0xffffffffu, ss, o);
    if((t&31)==0) sb[t>>5] = ss;
    __syncthreads();
    float inv = 1.f/fmaxf(sqrtf(sb[2*g]+sb[2*g+1]), 1e-12f);
    d_gn[r*DD + d] = v*inv;
}

// ---------------- K10: S[4096,8192] = Gn[:BN] @ Gn^T, FFMA2 -----------------
__global__ void k_sgemm(){
    __shared__ float As[64][68];   // [k][m]  (transposed on load)
    __shared__ float Bs[64][68];   // [k][n]
    int t = threadIdx.x;
    int j0 = blockIdx.x*64, i0 = blockIdx.y*64;
    #pragma unroll
    for(int u=0; u<4; u++){
        int f = t*4 + u; int rr = f>>4; int cq = f&15;
        float4 va = *(const float4*)&d_gn[(i0+rr)*DD + cq*4];
        As[cq*4+0][rr]=va.x; As[cq*4+1][rr]=va.y; As[cq*4+2][rr]=va.z; As[cq*4+3][rr]=va.w;
        float4 vb = *(const float4*)&d_gn[(j0+rr)*DD + cq*4];
        Bs[cq*4+0][rr]=vb.x; Bs[cq*4+1][rr]=vb.y; Bs[cq*4+2][rr]=vb.z; Bs[cq*4+3][rr]=vb.w;
    }
    __syncthreads();
    int tx = t & 7, ty = t >> 3;   // tx: n octet, ty: m pair
    ull cp[2][4] = {};
    #pragma unroll
    for(int k=0; k<64; k++){
        float2 a = *(float2*)&As[k][ty*2];
        ull a0 = rep2(a.x), a1 = rep2(a.y);
        ulonglong2 b01 = *(ulonglong2*)&Bs[k][tx*8];
        ulonglong2 b23 = *(ulonglong2*)&Bs[k][tx*8+4];
        cp[0][0]=ffma2(a0,b01.x,cp[0][0]); cp[0][1]=ffma2(a0,b01.y,cp[0][1]);
        cp[0][2]=ffma2(a0,b23.x,cp[0][2]); cp[0][3]=ffma2(a0,b23.y,cp[0][3]);
        cp[1][0]=ffma2(a1,b01.x,cp[1][0]); cp[1][1]=ffma2(a1,b01.y,cp[1][1]);
        cp[1][2]=ffma2(a1,b23.x,cp[1][2]); cp[1][3]=ffma2(a1,b23.y,cp[1][3]);
    }
    #pragma unroll
    for(int m=0;m<2;m++){
        int row = i0 + ty*2 + m;
        ulonglong2 o1; o1.x = cp[m][0]; o1.y = cp[m][1];
        ulonglong2 o2; o2.x = cp[m][2]; o2.y = cp[m][3];
        *(ulonglong2*)&d_S[(size_t)row*G2 + j0 + tx*8]     = o1;
        *(ulonglong2*)&d_S[(size_t)row*G2 + j0 + tx*8 + 4] = o2;
    }
}

// ---------------- K11: top-25 per row (register-resident) -------------------
__global__ void k_top25(){
    int r = blockIdx.x, t = threadIdx.x;     // 256 threads
    float4 v[8];
    #pragma unroll
    for(int u=0; u<8; u++)
        v[u] = *(const float4*)&d_S[(size_t)r*G2 + (t + u*256)*4];
    unsigned rem = 0;                         // removed-slot bitmask
    float bv; int bi;
    // local argmax (ascending idx scan; strict > keeps smallest idx)
    #define RESCAN() do{ \
        bv = -INFINITY; bi = 0x7fffffff; \
        _Pragma("unroll") \
        for(int u=0;u<8;u++){ \
            int base = 4*(t + u*256); \
            float x0 = (rem&(1u<<(u*4+0))) ? -INFINITY : v[u].x; if(x0>bv){bv=x0;bi=base;} \
            float x1 = (rem&(1u<<(u*4+1))) ? -INFINITY : v[u].y; if(x1>bv){bv=x1;bi=base+1;} \
            float x2 = (rem&(1u<<(u*4+2))) ? -INFINITY : v[u].z; if(x2>bv){bv=x2;bi=base+2;} \
            float x3 = (rem&(1u<<(u*4+3))) ? -INFINITY : v[u].w; if(x3>bv){bv=x3;bi=base+3;} \
        } }while(0)
    RESCAN();
    __shared__ float swv[8];
    __shared__ int   swi[8];
    __shared__ float gwv_s; __shared__ int gwi_s;
    for(int it=0; it<EX; it++){
        float wv = bv; int wi = bi;
        #pragma unroll
        for(int o=16;o>0;o>>=1){
            float ov = __shfl_down_sync(0xffffffffu, wv, o);
            int   oi = __shfl_down_sync(0xffffffffu, wi, o);
            if(ov > wv || (ov == wv && oi < wi)){ wv = ov; wi = oi; }
        }
        if((t&31)==0){ swv[t>>5] = wv; swi[t>>5] = wi; }
        __syncthreads();
        if(t==0){
            float m = swv[0]; int mi = swi[0];
            #pragma unroll
            for(int w=1;w<8;w++){
                if(swv[w] > m || (swv[w] == m && swi[w] < mi)){ m = swv[w]; mi = swi[w]; }
            }
            gwv_s = m; gwi_s = mi;
            d_topv2[r*EX+it] = m;
            d_topi2[r*EX+it] = mi;
        }
        __syncthreads();
        int gi = gwi_s;
        int q = gi >> 2;                  // owning float4 index
        if(t == (q & 255)){
            rem |= 1u << (((q >> 8) << 2) | (gi & 3));
            RESCAN();
        }
    }
    #undef RESCAN
}

// ---------------- K12: h2 = g[:BN] @ W2 + attention scalars (4 rows/blk) ----
__global__ void k_h2(const float* __restrict__ W2,
                     const float* __restrict__ ai2, const float* __restrict__ aj2){
    int t = threadIdx.x;
    int g = t>>6, d = t&63;
    int r = blockIdx.x*4 + g;
    __shared__ float sg[4][DD];
    __shared__ float svi[8], svj[8];
    sg[g][d] = d_g[r*DD + d];
    __syncthreads();
    float h = 0.f;
    #pragma unroll
    for(int k=0;k<DD;k++) h += sg[g][k]*W2[k*DD + d];
    d_h2[r*DD + d] = h;
    float vi = h*ai2[d], vj = h*aj2[d];
    #pragma unroll
    for(int o=16;o>0;o>>=1){
        vi += __shfl_down_sync(0xffffffffu, vi, o);
        vj += __shfl_down_sync(0xffffffffu, vj, o);
    }
    if((t&31)==0){ svi[t>>5]=vi; svj[t>>5]=vj; }
    __syncthreads();
    if(d==0){ d_hi2[r] = svi[2*g]+svi[2*g+1]; d_hj2[r] = svj[2*g]+svj[2*g+1]; }
}

// ---------------- K13-15: CSR build over kept layer-2 edges -----------------
__global__ void k_hist(){
    int e = blockIdx.x*256 + threadIdx.x;
    int dst = d_topi2[e];
    if(dst < BNN) atomicAdd(&d_cnt[dst], 1);
}
__global__ void k_scan(){       // single block, 256 threads
    __shared__ int ss[256];
    int t = threadIdx.x;
    int c[16]; int s = 0;
    #pragma unroll
    for(int i=0;i<16;i++){ int x = d_cnt[t*16+i]; c[i] = s; s += x; }
    ss[t] = s;
    __syncthreads();
    for(int off=1; off<256; off<<=1){
        int v = (t>=off) ? ss[t-off] : 0;
        __syncthreads();
        ss[t] += v;
        __syncthreads();
    }
    int base = (t==0) ? 0 : ss[t-1];
    #pragma unroll
    for(int i=0;i<16;i++) d_off[t*16+i] = base + c[i];
    if(t==255) d_off[BNN] = ss[255];
}
__global__ void k_scatter(){
    int e = blockIdx.x*256 + threadIdx.x;
    int dst = d_topi2[e];
    if(dst < BNN){
        int p = atomicAdd(&d_cur[dst], 1);
        d_eid[d_off[dst] + p] = e;
    }
}

// ---------------- K16: fused per-segment softmax + gather aggregation -------
__global__ void k_seg(){
    int r = blockIdx.x, t = threadIdx.x;    // 64 threads
    int start = d_off[r], end = d_off[r+1];
    __shared__ float sred[2];
    __shared__ float sal[64];
    __shared__ int   ssrc[64];
    float hi = d_hi2[r];
    float m = -INFINITY;
    for(int e=start+t; e<end; e+=64){
        int eid = d_eid[e]; int src = eid/EX;
        float sc = lrelu(hi + d_hj2[src]) * d_topv2[eid];
        d_sc2[e] = sc;
        m = fmaxf(m, sc);
    }
    #pragma unroll
    for(int o=16;o>0;o>>=1) m = fmaxf(m, __shfl_down_sync(0xffffffffu, m, o));
    if((t&31)==0) sred[t>>5] = m;
    __syncthreads();
    m = fmaxf(sred[0], sred[1]);
    __syncthreads();
    float s = 0.f;
    for(int e=start+t; e<end; e+=64) s += expf(d_sc2[e]-m);
    #pragma unroll
    for(int o=16;o>0;o>>=1) s += __shfl_down_sync(0xffffffffu, s, o);
    if((t&31)==0) sred[t>>5] = s;
    __syncthreads();
    float inv = 1.f/fmaxf(sred[0]+sred[1], 1e-12f);
    float acc = 0.f;
    for(int c0=start; c0<end; c0+=64){
        __syncthreads();
        int e = c0 + t;
        if(e < end){
            int eid = d_eid[e];
            ssrc[t] = eid/EX;
            sal[t]  = expf(d_sc2[e]-m)*inv;
        }
        __syncthreads();
        int cnt = min(64, end - c0);
        for(int k=0;k<cnt;k++) acc += sal[k]*d_h2[ssrc[k]*DD + t];
    }
    d_agg2[r*DD + t] = acc;
}

// ---------------- K17: x3 = relu(agg2+bias2)*emb ----------------
__global__ void k_x3(const float* __restrict__ bias2, const float* __restrict__ emb){
    int idx = blockIdx.x*256 + threadIdx.x;
    int r = idx >> 6, d = idx & 63;
    float v = fmaxf(d_agg2[idx] + bias2[d], 0.f);
    d_x3[idx] = v * emb[(r & (NN-1))*DD + d];
}

__global__ void k_stats2(const float* __restrict__ gamma, const float* __restrict__ beta){
    int d = blockIdx.x, t = threadIdx.x;
    __shared__ float sb[8];
    __shared__ float smu;
    float s = 0.f;
    for(int r=t; r<BNN; r+=256) s += d_x3[r*DD + d];
    #pragma unroll
    for(int o=16;o>0;o>>=1) s += __shfl_down_sync(0xffffffffu, s, o);
    if((t&31)==0) sb[t>>5] = s;
    __syncthreads();
    if(t==0){ float tot=0; for(int w=0;w<8;w++) tot+=sb[w]; smu = tot*(1.f/BNN); }
    __syncthreads();
    float mu = smu;
    float q = 0.f;
    for(int r=t; r<BNN; r+=256){ float x = d_x3[r*DD + d] - mu; q += x*x; }
    #pragma unroll
    for(int o=16;o>0;o>>=1) q += __shfl_down_sync(0xffffffffu, q, o);
    if((t&31)==0) sb[t>>5] = q;
    __syncthreads();
    if(t==0){
        float tot=0; for(int w=0;w<8;w++) tot+=sb[w];
        float var = tot*(1.f/BNN);
        float sc  = gamma[d]/sqrtf(var + 1e-5f);
        d_scale2[d] = sc; d_shift2[d] = beta[d] - mu*sc;
    }
}

// ---------------- K19: output head (4 rows/block) ----------------
__global__ void k_out(const float* __restrict__ Wout, const float* __restrict__ bout,
                      float* __restrict__ out){
    int t = threadIdx.x;
    int g = t>>6, d = t&63;
    int r = blockIdx.x*4 + g;
    __shared__ float sb[8];
    float x = fmaxf(d_scale2[d]*d_x3[r*DD + d] + d_shift2[d], 0.f);
    float v = x * Wout[d];
    #pragma unroll
    for(int o=16;o>0;o>>=1) v += __shfl_down_sync(0xffffffffu, v, o);
    if((t&31)==0) sb[t>>5] = v;
    __syncthreads();
    if(d==0) out[r] = sb[2*g]+sb[2*g+1] + bout[0];
}

// ---------------- launch ----------------
extern "C" void kernel_launch(void* const* d_in, const int* in_sizes, int n_in,
                              void* d_out, int out_size){
    (void)in_sizes; (void)n_in; (void)out_size;
    const float* data  = (const float*)d_in[0];
    const float* emb   = (const float*)d_in[1];
    const float* W1    = (const float*)d_in[2];
    const float* ai1   = (const float*)d_in[3];
    const float* aj1   = (const float*)d_in[4];
    const float* bias1 = (const float*)d_in[5];
    const float* bn1g  = (const float*)d_in[6];
    const float* bn1b  = (const float*)d_in[7];
    const float* P     = (const float*)d_in[8];
    const float* W2    = (const float*)d_in[9];
    const float* ai2   = (const float*)d_in[10];
    const float* aj2   = (const float*)d_in[11];
    const float* bias2 = (const float*)d_in[12];
    const float* bnOg  = (const float*)d_in[13];
    const float* bnOb  = (const float*)d_in[14];
    const float* Wout  = (const float*)d_in[15];
    const float* bout  = (const float*)d_in[16];
    float* out = (float*)d_out;

    k_zero   <<<17, 256>>>();
    k_embprep<<<NN, DD>>>(emb, ai1, aj1);
    k_cos1   <<<NN, NN>>>(emb);
    k_h      <<<BNN/4, 256>>>(data, W1, ai1, aj1);
    k_attn1  <<<BNN/4, 256>>>(bias1);
    k_stats1 <<<DD, 256>>>(bn1g, bn1b);
    k_bnrelu <<<BNN*DD/256, 256>>>();
    k_ef     <<<dim3(64, NSLICE), 256>>>(P);
    k_gnorm  <<<G2/4, 256>>>();
    k_sgemm  <<<dim3(128, 64), 256>>>();
    k_top25  <<<BNN, 256>>>();
    k_h2     <<<BNN/4, 256>>>(W2, ai2, aj2);
    k_hist   <<<NE/256, 256>>>();
    k_scan   <<<1, 256>>>();
    k_scatter<<<NE/256, 256>>>();
    k_seg    <<<BNN, 64>>>();
    k_x3     <<<BNN*DD/256, 256>>>(bias2, emb);
    k_stats2 <<<DD, 256>>>(bnOg, bnOb);
    k_out    <<<BNN/4, 256>>>(Wout, bout, out);
}

// round 5
// speedup vs baseline: 1.3040x; 1.3040x over previous
#include <cuda_runtime.h>
#include <math.h>

#define BB 32
#define NN 128
#define FF 10
#define DD 64
#define TK 20
#define EX 25
#define BNN 4096           // B*N
#define G2 8192            // 2*BN
#define NE (BNN*EX)        // 102400 candidate edges in layer 2
#define NSLICE 8

// ---------------- scratch (device globals: allocation-free) ----------------
__device__ float d_h[BNN*DD];
__device__ float d_si[BNN], d_sj[BNN];
__device__ float d_ei[NN], d_ej[NN], d_invn1[NN];
__device__ int   d_topi1[NN*TK];
__device__ float d_topv1[NN*TK];
__device__ float d_agg[BNN*DD];
__device__ float d_scale1[DD], d_shift1[DD];
__device__ float d_g[BNN*DD];               // gcn rows only
__device__ float d_efp[NSLICE*BNN*DD];      // ef partial sums per K-slice
__device__ float d_gn[G2*DD];               // row-normalized [gcn; ef]
__device__ float d_h2[BNN*DD];
__device__ float d_hi2[BNN], d_hj2[BNN];
__device__ float d_S[(size_t)BNN*G2];       // 128 MB cosine-score matrix
__device__ int   d_topi2[NE];
__device__ float d_topv2[NE];
__device__ int   d_cnt[BNN];
__device__ int   d_cur[BNN];
__device__ int   d_off[BNN+1];
__device__ int   d_eid[NE];
__device__ float d_sc2[NE];
__device__ float d_x3[BNN*DD];
__device__ float d_scale2[DD], d_shift2[DD];

// ---------------- helpers ----------------
__device__ __forceinline__ float lrelu(float x){ return x >= 0.f ? x : 0.2f*x; }

typedef unsigned long long ull;
__device__ __forceinline__ ull ffma2(ull a, ull b, ull c){
    ull d; asm("fma.rn.f32x2 %0, %1, %2, %3;" : "=l"(d) : "l"(a), "l"(b), "l"(c));
    return d;
}
__device__ __forceinline__ ull rep2(float x){
    ull d; asm("mov.b64 %0, {%1, %1};" : "=l"(d) : "r"(__float_as_uint(x)));
    return d;
}

// ---------------- K0: zero CSR counters ----------------
__global__ void k_zero(){
    int idx = blockIdx.x*256 + threadIdx.x;
    if(idx < BNN){ d_cnt[idx] = 0; d_cur[idx] = 0; }
}

// ---------------- K1: emb norms + embedding parts of attention keys ----------
__global__ void k_embprep(const float* __restrict__ emb,
                          const float* __restrict__ ai1,
                          const float* __restrict__ aj1){
    int n = blockIdx.x, t = threadIdx.x;
    float e  = emb[n*DD + t];
    float ss = e*e, vi = e*ai1[DD+t], vj = e*aj1[DD+t];
    __shared__ float sb[6];
    #pragma unroll
    for(int o=16;o>0;o>>=1){
        ss += __shfl_down_sync(0xffffffffu, ss, o);
        vi += __shfl_down_sync(0xffffffffu, vi, o);
        vj += __shfl_down_sync(0xffffffffu, vj, o);
    }
    if((t&31)==0){ int w=t>>5; sb[w]=ss; sb[2+w]=vi; sb[4+w]=vj; }
    __syncthreads();
    if(t==0){
        float nrm = sqrtf(sb[0]+sb[1]);
        d_invn1[n] = 1.f/fmaxf(nrm, 1e-12f);
        d_ei[n] = sb[2]+sb[3];
        d_ej[n] = sb[4]+sb[5];
    }
}

// ---------------- K2: cosine(emb,emb) + top-20 per node ----------------
__global__ void k_cos1(const float* __restrict__ emb){
    int i = blockIdx.x, t = threadIdx.x;            // 128 threads
    __shared__ float se[DD];
    __shared__ float sc[NN];
    __shared__ float rv[NN];
    __shared__ int   ridx[NN];
    if(t < DD) se[t] = emb[i*DD + t];
    __syncthreads();
    float dp = 0.f;
    #pragma unroll
    for(int d=0; d<DD; d++) dp += se[d]*emb[t*DD + d];
    sc[t] = dp * d_invn1[i] * d_invn1[t];
    __syncthreads();
    for(int it=0; it<TK; it++){
        rv[t] = sc[t]; ridx[t] = t;
        __syncthreads();
        for(int s=64; s>0; s>>=1){
            if(t < s){
                float v2 = rv[t+s]; int i2 = ridx[t+s];
                if(v2 > rv[t] || (v2 == rv[t] && i2 < ridx[t])){ rv[t]=v2; ridx[t]=i2; }
            }
            __syncthreads();
        }
        if(t==0){
            d_topv1[i*TK+it] = rv[0];
            d_topi1[i*TK+it] = ridx[0];
            sc[ridx[0]] = -INFINITY;
        }
        __syncthreads();
    }
}

// ---------------- K3: h = x@W1, si/sj scalars (4 rows/block) ----------------
__global__ void k_h(const float* __restrict__ data, const float* __restrict__ W1,
                    const float* __restrict__ ai1, const float* __restrict__ aj1){
    int t = threadIdx.x;
    int g = t>>6, d = t&63;
    int r = blockIdx.x*4 + g;
    __shared__ float sx[4][FF];
    __shared__ float svi[8], svj[8];
    if(d < FF) sx[g][d] = data[r*FF + d];
    __syncthreads();
    float h = 0.f;
    #pragma unroll
    for(int f=0; f<FF; f++) h += sx[g][f]*W1[f*DD + d];
    d_h[r*DD + d] = h;
    float vi = h*ai1[d], vj = h*aj1[d];
    #pragma unroll
    for(int o=16;o>0;o>>=1){
        vi += __shfl_down_sync(0xffffffffu, vi, o);
        vj += __shfl_down_sync(0xffffffffu, vj, o);
    }
    if((t&31)==0){ svi[t>>5]=vi; svj[t>>5]=vj; }
    __syncthreads();
    if(d==0){
        d_si[r] = svi[2*g]+svi[2*g+1] + d_ei[r & (NN-1)];
        d_sj[r] = svj[2*g]+svj[2*g+1] + d_ej[r & (NN-1)];
    }
}

// ---------------- K4: layer-1 edge softmax + aggregation (4 rows/block) -----
__global__ void k_attn1(const float* __restrict__ bias1){
    int t = threadIdx.x;
    int g = t>>6, d = t&63;
    int r = blockIdx.x*4 + g;
    int b = r >> 7, i = r & (NN-1);
    __shared__ int   ssrc[4][TK];
    __shared__ float sal[4][TK];
    if(d < TK){
        int sn = d_topi1[i*TK + d];
        int s  = (b<<7) + sn;
        ssrc[g][d] = s;
        sal[g][d]  = lrelu(d_si[r] + d_sj[s]) * d_topv1[i*TK + d];
    }
    __syncthreads();
    if(d == 0){
        float m = -INFINITY;
        for(int k=0;k<TK;k++) m = fmaxf(m, sal[g][k]);
        float e[TK], sum = 0.f;
        for(int k=0;k<TK;k++){ e[k] = expf(sal[g][k]-m); sum += e[k]; }
        float inv = 1.f/fmaxf(sum, 1e-12f);
        for(int k=0;k<TK;k++) sal[g][k] = e[k]*inv;
    }
    __syncthreads();
    float a = 0.f;
    #pragma unroll
    for(int k=0;k<TK;k++) a += sal[g][k]*d_h[ssrc[g][k]*DD + d];
    d_agg[r*DD + d] = a + bias1[d];
}

// ---------------- batchnorm stats (two-pass, per channel) ----------------
__global__ void k_stats1(const float* __restrict__ gamma, const float* __restrict__ beta){
    int d = blockIdx.x, t = threadIdx.x;            // 256 threads
    __shared__ float sb[8];
    __shared__ float smu;
    float s = 0.f;
    for(int r=t; r<BNN; r+=256) s += d_agg[r*DD + d];
    #pragma unroll
    for(int o=16;o>0;o>>=1) s += __shfl_down_sync(0xffffffffu, s, o);
    if((t&31)==0) sb[t>>5] = s;
    __syncthreads();
    if(t==0){ float tot=0; for(int w=0;w<8;w++) tot+=sb[w]; smu = tot*(1.f/BNN); }
    __syncthreads();
    float mu = smu;
    float q = 0.f;
    for(int r=t; r<BNN; r+=256){ float x = d_agg[r*DD + d] - mu; q += x*x; }
    #pragma unroll
    for(int o=16;o>0;o>>=1) q += __shfl_down_sync(0xffffffffu, q, o);
    if((t&31)==0) sb[t>>5] = q;
    __syncthreads();
    if(t==0){
        float tot=0; for(int w=0;w<8;w++) tot+=sb[w];
        float var = tot*(1.f/BNN);
        float sc  = gamma[d]/sqrtf(var + 1e-5f);
        d_scale1[d] = sc; d_shift1[d] = beta[d] - mu*sc;
    }
}

__global__ void k_bnrelu(){
    int idx = blockIdx.x*256 + threadIdx.x;
    int d = idx & 63;
    d_g[idx] = fmaxf(d_scale1[d]*d_agg[idx] + d_shift1[d], 0.f);
}

// ---------------- K8: ef = P^T @ gcn (64-j tiles, 8 K-slices, prefetch) -----
__global__ void __launch_bounds__(128) k_ef(const float* __restrict__ P){
    __shared__ float As[64][68];   // [k_local][j_local] = P[k][j0+j]
    __shared__ float Bs[64][68];   // [k_local][d]       = gcn[k][d]
    int t = threadIdx.x;
    int j0 = blockIdx.x*64;
    int slice = blockIdx.y;
    int tx = t & 7, ty = t >> 3;   // tx: d octet, ty: j quad
    float4 pa[8], pb[8];
    int ib = slice*512;
    #pragma unroll
    for(int u=0; u<8; u++){
        int f = t*8+u; int k = f>>4; int cq = f&15;
        pa[u] = *(const float4*)&P[(size_t)(ib+k)*BNN + j0 + cq*4];
        pb[u] = *(const float4*)&d_g[(ib+k)*DD + cq*4];
    }
    ull cp[4][4] = {};
    for(int cc=0; cc<8; cc++){
        #pragma unroll
        for(int u=0; u<8; u++){
            int f = t*8+u; int k = f>>4; int cq = f&15;
            *(float4*)&As[k][cq*4] = pa[u];
            *(float4*)&Bs[k][cq*4] = pb[u];
        }
        __syncthreads();
        if(cc < 7){
            int ib2 = slice*512 + (cc+1)*64;
            #pragma unroll
            for(int u=0; u<8; u++){
                int f = t*8+u; int k = f>>4; int cq = f&15;
                pa[u] = *(const float4*)&P[(size_t)(ib2+k)*BNN + j0 + cq*4];
                pb[u] = *(const float4*)&d_g[(ib2+k)*DD + cq*4];
            }
        }
        #pragma unroll
        for(int k=0; k<64; k++){
            float4 a = *(float4*)&As[k][ty*4];
            ulonglong2 b01 = *(ulonglong2*)&Bs[k][tx*8];
            ulonglong2 b23 = *(ulonglong2*)&Bs[k][tx*8+4];
            ull ra;
            ra = rep2(a.x);
            cp[0][0]=ffma2(ra,b01.x,cp[0][0]); cp[0][1]=ffma2(ra,b01.y,cp[0][1]);
            cp[0][2]=ffma2(ra,b23.x,cp[0][2]); cp[0][3]=ffma2(ra,b23.y,cp[0][3]);
            ra = rep2(a.y);
            cp[1][0]=ffma2(ra,b01.x,cp[1][0]); cp[1][1]=ffma2(ra,b01.y,cp[1][1]);
            cp[1][2]=ffma2(ra,b23.x,cp[1][2]); cp[1][3]=ffma2(ra,b23.y,cp[1][3]);
            ra = rep2(a.z);
            cp[2][0]=ffma2(ra,b01.x,cp[2][0]); cp[2][1]=ffma2(ra,b01.y,cp[2][1]);
            cp[2][2]=ffma2(ra,b23.x,cp[2][2]); cp[2][3]=ffma2(ra,b23.y,cp[2][3]);
            ra = rep2(a.w);
            cp[3][0]=ffma2(ra,b01.x,cp[3][0]); cp[3][1]=ffma2(ra,b01.y,cp[3][1]);
            cp[3][2]=ffma2(ra,b23.x,cp[3][2]); cp[3][3]=ffma2(ra,b23.y,cp[3][3]);
        }
        __syncthreads();
    }
    float* outp = &d_efp[(size_t)slice*BNN*DD];
    #pragma unroll
    for(int m=0;m<4;m++){
        int row = j0 + ty*4 + m;
        ulonglong2 o1; o1.x = cp[m][0]; o1.y = cp[m][1];
        ulonglong2 o2; o2.x = cp[m][2]; o2.y = cp[m][3];
        *(ulonglong2*)&outp[row*DD + tx*8]     = o1;
        *(ulonglong2*)&outp[row*DD + tx*8 + 4] = o2;
    }
}

// ---------------- K9: row-normalize [gcn; ef] (4 rows/block) ----------------
__global__ void k_gnorm(){
    int t = threadIdx.x;
    int g = t>>6, d = t&63;
    int r = blockIdx.x*4 + g;
    __shared__ float sb[8];
    float v;
    if(r < BNN) v = d_g[r*DD + d];
    else {
        int rr = r - BNN;
        v = 0.f;
        #pragma unroll
        for(int s=0; s<NSLICE; s++) v += d_efp[(size_t)s*BNN*DD + rr*DD + d];
    }
    float ss = v*v;
    #pragma unroll
    for(int o=16;o>0;o>>=1) ss += __shfl_down_sync(0xffffffffu, ss, o);
    if((t&31)==0) sb[t>>5] = ss;
    __syncthreads();
    float inv = 1.f/fmaxf(sqrtf(sb[2*g]+sb[2*g+1]), 1e-12f);
    d_gn[r*DD + d] = v*inv;
}

// ---------------- K10: S[4096,8192] = Gn[:BN] @ Gn^T (128x64 tiles) ---------
__global__ void __launch_bounds__(128) k_sgemm(){
    __shared__ float As[64][132];  // [d][m] m=128, transposed on load
    __shared__ float Bs[64][68];   // [d][n] n=64,  transposed on load
    int t = threadIdx.x;
    int j0 = blockIdx.x*64, i0 = blockIdx.y*128;
    // A: thread t owns row i0+t, 16 float4s, store transposed
    #pragma unroll
    for(int u=0; u<16; u++){
        float4 va = *(const float4*)&d_gn[(i0+t)*DD + u*4];
        As[u*4+0][t]=va.x; As[u*4+1][t]=va.y; As[u*4+2][t]=va.z; As[u*4+3][t]=va.w;
    }
    #pragma unroll
    for(int u=0; u<8; u++){
        int f = t*8+u; int rr = f>>4; int cq = f&15;
        float4 vb = *(const float4*)&d_gn[(j0+rr)*DD + cq*4];
        Bs[cq*4+0][rr]=vb.x; Bs[cq*4+1][rr]=vb.y; Bs[cq*4+2][rr]=vb.z; Bs[cq*4+3][rr]=vb.w;
    }
    __syncthreads();
    int tx = t & 7, ty = t >> 3;   // tx: n octet, ty: m octet (16)
    ull cp[8][4] = {};
    #pragma unroll
    for(int k=0; k<64; k++){
        float4 a0 = *(float4*)&As[k][ty*8];
        float4 a1 = *(float4*)&As[k][ty*8+4];
        ulonglong2 b01 = *(ulonglong2*)&Bs[k][tx*8];
        ulonglong2 b23 = *(ulonglong2*)&Bs[k][tx*8+4];
        ull ra;
        ra=rep2(a0.x);
        cp[0][0]=ffma2(ra,b01.x,cp[0][0]); cp[0][1]=ffma2(ra,b01.y,cp[0][1]);
        cp[0][2]=ffma2(ra,b23.x,cp[0][2]); cp[0][3]=ffma2(ra,b23.y,cp[0][3]);
        ra=rep2(a0.y);
        cp[1][0]=ffma2(ra,b01.x,cp[1][0]); cp[1][1]=ffma2(ra,b01.y,cp[1][1]);
        cp[1][2]=ffma2(ra,b23.x,cp[1][2]); cp[1][3]=ffma2(ra,b23.y,cp[1][3]);
        ra=rep2(a0.z);
        cp[2][0]=ffma2(ra,b01.x,cp[2][0]); cp[2][1]=ffma2(ra,b01.y,cp[2][1]);
        cp[2][2]=ffma2(ra,b23.x,cp[2][2]); cp[2][3]=ffma2(ra,b23.y,cp[2][3]);
        ra=rep2(a0.w);
        cp[3][0]=ffma2(ra,b01.x,cp[3][0]); cp[3][1]=ffma2(ra,b01.y,cp[3][1]);
        cp[3][2]=ffma2(ra,b23.x,cp[3][2]); cp[3][3]=ffma2(ra,b23.y,cp[3][3]);
        ra=rep2(a1.x);
        cp[4][0]=ffma2(ra,b01.x,cp[4][0]); cp[4][1]=ffma2(ra,b01.y,cp[4][1]);
        cp[4][2]=ffma2(ra,b23.x,cp[4][2]); cp[4][3]=ffma2(ra,b23.y,cp[4][3]);
        ra=rep2(a1.y);
        cp[5][0]=ffma2(ra,b01.x,cp[5][0]); cp[5][1]=ffma2(ra,b01.y,cp[5][1]);
        cp[5][2]=ffma2(ra,b23.x,cp[5][2]); cp[5][3]=ffma2(ra,b23.y,cp[5][3]);
        ra=rep2(a1.z);
        cp[6][0]=ffma2(ra,b01.x,cp[6][0]); cp[6][1]=ffma2(ra,b01.y,cp[6][1]);
        cp[6][2]=ffma2(ra,b23.x,cp[6][2]); cp[6][3]=ffma2(ra,b23.y,cp[6][3]);
        ra=rep2(a1.w);
        cp[7][0]=ffma2(ra,b01.x,cp[7][0]); cp[7][1]=ffma2(ra,b01.y,cp[7][1]);
        cp[7][2]=ffma2(ra,b23.x,cp[7][2]); cp[7][3]=ffma2(ra,b23.y,cp[7][3]);
    }
    #pragma unroll
    for(int m=0;m<8;m++){
        int row = i0 + ty*8 + m;
        ulonglong2 o1; o1.x = cp[m][0]; o1.y = cp[m][1];
        ulonglong2 o2; o2.x = cp[m][2]; o2.y = cp[m][3];
        *(ulonglong2*)&d_S[(size_t)row*G2 + j0 + tx*8]     = o1;
        *(ulonglong2*)&d_S[(size_t)row*G2 + j0 + tx*8 + 4] = o2;
    }
}

// ---------------- K11: top-25 per row (register-resident, 1 bar/pick) -------
__global__ void k_top25(){
    int r = blockIdx.x, t = threadIdx.x;     // 256 threads
    float4 v[8];
    #pragma unroll
    for(int u=0; u<8; u++)
        v[u] = *(const float4*)&d_S[(size_t)r*G2 + (t + u*256)*4];
    unsigned rem = 0;
    float bv; int bi;
    #define RESCAN() do{ \
        bv = -INFINITY; bi = 0x7fffffff; \
        _Pragma("unroll") \
        for(int u=0;u<8;u++){ \
            int base = 4*(t + u*256); \
            float x0 = (rem&(1u<<(u*4+0))) ? -INFINITY : v[u].x; if(x0>bv){bv=x0;bi=base;} \
            float x1 = (rem&(1u<<(u*4+1))) ? -INFINITY : v[u].y; if(x1>bv){bv=x1;bi=base+1;} \
            float x2 = (rem&(1u<<(u*4+2))) ? -INFINITY : v[u].z; if(x2>bv){bv=x2;bi=base+2;} \
            float x3 = (rem&(1u<<(u*4+3))) ? -INFINITY : v[u].w; if(x3>bv){bv=x3;bi=base+3;} \
        } }while(0)
    RESCAN();
    __shared__ float swv[2][8];
    __shared__ int   swi[2][8];
    for(int it=0; it<EX; it++){
        float wv = bv; int wi = bi;
        #pragma unroll
        for(int o=16;o>0;o>>=1){
            float ov = __shfl_xor_sync(0xffffffffu, wv, o);
            int   oi = __shfl_xor_sync(0xffffffffu, wi, o);
            if(ov > wv || (ov == wv && oi < wi)){ wv = ov; wi = oi; }
        }
        int p = it & 1;
        if((t&31)==0){ swv[p][t>>5] = wv; swi[p][t>>5] = wi; }
        __syncthreads();
        float gm = swv[p][0]; int gi = swi[p][0];
        #pragma unroll
        for(int w=1;w<8;w++){
            if(swv[p][w] > gm || (swv[p][w] == gm && swi[p][w] < gi)){ gm = swv[p][w]; gi = swi[p][w]; }
        }
        if(t==0){
            d_topv2[r*EX+it] = gm;
            d_topi2[r*EX+it] = gi;
            if(gi < BNN) atomicAdd(&d_cnt[gi], 1);   // fused histogram
        }
        if(bi == gi){
            int q = gi >> 2;
            rem |= 1u << (((q >> 8) << 2) | (gi & 3));
            RESCAN();
        }
    }
    #undef RESCAN
}

// ---------------- K12: h2 = g[:BN] @ W2 + attention scalars (4 rows/blk) ----
__global__ void k_h2(const float* __restrict__ W2,
                     const float* __restrict__ ai2, const float* __restrict__ aj2){
    int t = threadIdx.x;
    int g = t>>6, d = t&63;
    int r = blockIdx.x*4 + g;
    __shared__ float sg[4][DD];
    __shared__ float svi[8], svj[8];
    sg[g][d] = d_g[r*DD + d];
    __syncthreads();
    float h = 0.f;
    #pragma unroll
    for(int k=0;k<DD;k++) h += sg[g][k]*W2[k*DD + d];
    d_h2[r*DD + d] = h;
    float vi = h*ai2[d], vj = h*aj2[d];
    #pragma unroll
    for(int o=16;o>0;o>>=1){
        vi += __shfl_down_sync(0xffffffffu, vi, o);
        vj += __shfl_down_sync(0xffffffffu, vj, o);
    }
    if((t&31)==0){ svi[t>>5]=vi; svj[t>>5]=vj; }
    __syncthreads();
    if(d==0){ d_hi2[r] = svi[2*g]+svi[2*g+1]; d_hj2[r] = svj[2*g]+svj[2*g+1]; }
}

// ---------------- K13/K14: CSR build (scan + scatter) -----------------------
__global__ void k_scan(){       // single block, 256 threads
    __shared__ int ss[256];
    int t = threadIdx.x;
    int c[16]; int s = 0;
    #pragma unroll
    for(int i=0;i<16;i++){ int x = d_cnt[t*16+i]; c[i] = s; s += x; }
    ss[t] = s;
    __syncthreads();
    for(int off=1; off<256; off<<=1){
        int v = (t>=off) ? ss[t-off] : 0;
        __syncthreads();
        ss[t] += v;
        __syncthreads();
    }
    int base = (t==0) ? 0 : ss[t-1];
    #pragma unroll
    for(int i=0;i<16;i++) d_off[t*16+i] = base + c[i];
    if(t==255) d_off[BNN] = ss[255];
}
__global__ void k_scatter(){
    int e = blockIdx.x*256 + threadIdx.x;
    int dst = d_topi2[e];
    if(dst < BNN){
        int p = atomicAdd(&d_cur[dst], 1);
        d_eid[d_off[dst] + p] = e;
    }
}

// ---------------- K15: fused segment softmax + gather + x3 ------------------
__global__ void k_seg(const float* __restrict__ bias2, const float* __restrict__ emb){
    int r = blockIdx.x, t = threadIdx.x;    // 64 threads
    int start = d_off[r], end = d_off[r+1];
    __shared__ float sred[2];
    __shared__ float sal[64];
    __shared__ int   ssrc[64];
    float hi = d_hi2[r];
    float m = -INFINITY;
    for(int e=start+t; e<end; e+=64){
        int eid = d_eid[e]; int src = eid/EX;
        float sc = lrelu(hi + d_hj2[src]) * d_topv2[eid];
        d_sc2[e] = sc;
        m = fmaxf(m, sc);
    }
    #pragma unroll
    for(int o=16;o>0;o>>=1) m = fmaxf(m, __shfl_down_sync(0xffffffffu, m, o));
    if((t&31)==0) sred[t>>5] = m;
    __syncthreads();
    m = fmaxf(sred[0], sred[1]);
    __syncthreads();
    float s = 0.f;
    for(int e=start+t; e<end; e+=64) s += expf(d_sc2[e]-m);
    #pragma unroll
    for(int o=16;o>0;o>>=1) s += __shfl_down_sync(0xffffffffu, s, o);
    if((t&31)==0) sred[t>>5] = s;
    __syncthreads();
    float inv = 1.f/fmaxf(sred[0]+sred[1], 1e-12f);
    float acc = 0.f;
    for(int c0=start; c0<end; c0+=64){
        __syncthreads();
        int e = c0 + t;
        if(e < end){
            int eid = d_eid[e];
            ssrc[t] = eid/EX;
            sal[t]  = expf(d_sc2[e]-m)*inv;
        }
        __syncthreads();
        int cnt = min(64, end - c0);
        for(int k=0;k<cnt;k++) acc += sal[k]*d_h2[ssrc[k]*DD + t];
    }
    // fused: x3 = relu(acc + bias2) * emb
    float x = fmaxf(acc + bias2[t], 0.f);
    d_x3[r*DD + t] = x * emb[(r & (NN-1))*DD + t];
}

__global__ void k_stats2(const float* __restrict__ gamma, const float* __restrict__ beta){
    int d = blockIdx.x, t = threadIdx.x;
    __shared__ float sb[8];
    __shared__ float smu;
    float s = 0.f;
    for(int r=t; r<BNN; r+=256) s += d_x3[r*DD + d];
    #pragma unroll
    for(int o=16;o>0;o>>=1) s += __shfl_down_sync(0xffffffffu, s, o);
    if((t&31)==0) sb[t>>5] = s;
    __syncthreads();
    if(t==0){ float tot=0; for(int w=0;w<8;w++) tot+=sb[w]; smu = tot*(1.f/BNN); }
    __syncthreads();
    float mu = smu;
    float q = 0.f;
    for(int r=t; r<BNN; r+=256){ float x = d_x3[r*DD + d] - mu; q += x*x; }
    #pragma unroll
    for(int o=16;o>0;o>>=1) q += __shfl_down_sync(0xffffffffu, q, o);
    if((t&31)==0) sb[t>>5] = q;
    __syncthreads();
    if(t==0){
        float tot=0; for(int w=0;w<8;w++) tot+=sb[w];
        float var = tot*(1.f/BNN);
        float sc  = gamma[d]/sqrtf(var + 1e-5f);
        d_scale2[d] = sc; d_shift2[d] = beta[d] - mu*sc;
    }
}

// ---------------- K17: output head (4 rows/block) ----------------
__global__ void k_out(const float* __restrict__ Wout, const float* __restrict__ bout,
                      float* __restrict__ out){
    int t = threadIdx.x;
    int g = t>>6, d = t&63;
    int r = blockIdx.x*4 + g;
    __shared__ float sb[8];
    float x = fmaxf(d_scale2[d]*d_x3[r*DD + d] + d_shift2[d], 0.f);
    float v = x * Wout[d];
    #pragma unroll
    for(int o=16;o>0;o>>=1) v += __shfl_down_sync(0xffffffffu, v, o);
    if((t&31)==0) sb[t>>5] = v;
    __syncthreads();
    if(d==0) out[r] = sb[2*g]+sb[2*g+1] + bout[0];
}

// ---------------- launch ----------------
extern "C" void kernel_launch(void* const* d_in, const int* in_sizes, int n_in,
                              void* d_out, int out_size){
    (void)in_sizes; (void)n_in; (void)out_size;
    const float* data  = (const float*)d_in[0];
    const float* emb   = (const float*)d_in[1];
    const float* W1    = (const float*)d_in[2];
    const float* ai1   = (const float*)d_in[3];
    const float* aj1   = (const float*)d_in[4];
    const float* bias1 = (const float*)d_in[5];
    const float* bn1g  = (const float*)d_in[6];
    const float* bn1b  = (const float*)d_in[7];
    const float* P     = (const float*)d_in[8];
    const float* W2    = (const float*)d_in[9];
    const float* ai2   = (const float*)d_in[10];
    const float* aj2   = (const float*)d_in[11];
    const float* bias2 = (const float*)d_in[12];
    const float* bnOg  = (const float*)d_in[13];
    const float* bnOb  = (const float*)d_in[14];
    const float* Wout  = (const float*)d_in[15];
    const float* bout  = (const float*)d_in[16];
    float* out = (float*)d_out;

    k_zero   <<<17, 256>>>();
    k_embprep<<<NN, DD>>>(emb, ai1, aj1);
    k_cos1   <<<NN, NN>>>(emb);
    k_h      <<<BNN/4, 256>>>(data, W1, ai1, aj1);
    k_attn1  <<<BNN/4, 256>>>(bias1);
    k_stats1 <<<DD, 256>>>(bn1g, bn1b);
    k_bnrelu <<<BNN*DD/256, 256>>>();
    k_ef     <<<dim3(64, NSLICE), 128>>>(P);
    k_gnorm  <<<G2/4, 256>>>();
    k_sgemm  <<<dim3(128, 32), 128>>>();
    k_top25  <<<BNN, 256>>>();
    k_h2     <<<BNN/4, 256>>>(W2, ai2, aj2);
    k_scan   <<<1, 256>>>();
    k_scatter<<<NE/256, 256>>>();
    k_seg    <<<BNN, 64>>>(bias2, emb);
    k_stats2 <<<DD, 256>>>(bnOg, bnOb);
    k_out    <<<BNN/4, 256>>>(Wout, bout, out);
}